// round 3
// baseline (speedup 1.0000x reference)
#include <cuda_runtime.h>

#define PP        4096
#define HH        256
#define NSTEPS    100
#define DTC       0.1f
#define SQRT_DTC  0.31622776601683794f
#define ROWS      8        // particles per block
#define NTHREADS  256      // 64 col-threads x 4 k-quarters
#define NBLOCKS   (PP / ROWS)   // 512

// Carried recurrent state (allocation-free scratch).
__device__ float g_state[PP * 2];

__device__ __forceinline__ float softplusf(float x) {
    // matches jax.nn.softplus == max(x,0) + log1p(exp(-|x|))
    return fmaxf(x, 0.0f) + log1pf(expf(-fabsf(x)));
}

__device__ __forceinline__ unsigned long long pack2(float lo, float hi) {
    unsigned long long r;
    asm("mov.b64 %0, {%1, %2};" : "=l"(r) : "f"(lo), "f"(hi));
    return r;
}
__device__ __forceinline__ void unpack2(unsigned long long v, float& lo, float& hi) {
    asm("mov.b64 {%0, %1}, %2;" : "=f"(lo), "=f"(hi) : "l"(v));
}
// packed fp32 pair ops (2 lanes per instruction on sm_103a)
__device__ __forceinline__ void fma2(unsigned long long& d, unsigned long long a,
                                     unsigned long long b) {
    asm("fma.rn.f32x2 %0, %1, %2, %0;" : "+l"(d) : "l"(a), "l"(b));
}
__device__ __forceinline__ unsigned long long add2(unsigned long long a,
                                                   unsigned long long b) {
    unsigned long long r;
    asm("add.rn.f32x2 %0, %1, %2;" : "=l"(r) : "l"(a), "l"(b));
    return r;
}

// One 256->256 layer with relu: act[n_in][r] (8 rows) -> nxt[n_out][r].
// Thread (t = tid&63, q = tid>>6): 4 output cols n0=4t.., k-range [64q, 64q+64).
// Per k: 1 LDG.128 (4 weights) + 2 broadcast LDS.128 + 16 FFMA2.
// partial: [16 accs][3 quarters][64 threads] for the cross-quarter reduction.
__device__ __forceinline__ void mlp_layer(const float* act, float* nxt,
                                          const float* __restrict__ W,
                                          const float* __restrict__ b,
                                          unsigned long long* partial, int tid) {
    const int t  = tid & 63;
    const int q  = tid >> 6;
    const int n0 = 4 * t;
    const int k0 = q * 64;

    unsigned long long acc[4][4];
    if (q == 0) {
        float4 bv = *reinterpret_cast<const float4*>(b + n0);
#pragma unroll
        for (int i = 0; i < 4; i++) {
            acc[0][i] = pack2(bv.x, bv.x);
            acc[1][i] = pack2(bv.y, bv.y);
            acc[2][i] = pack2(bv.z, bv.z);
            acc[3][i] = pack2(bv.w, bv.w);
        }
    } else {
#pragma unroll
        for (int c = 0; c < 4; c++)
#pragma unroll
            for (int i = 0; i < 4; i++) acc[c][i] = 0ull;
    }

    const float4* wp = reinterpret_cast<const float4*>(W) + k0 * (HH / 4) + t;
    const float*  ab = act + k0 * ROWS;
#pragma unroll 4
    for (int k = 0; k < 64; k++) {
        float4 wv = __ldg(wp + k * (HH / 4));     // 4 adjacent weights, coalesced
        unsigned long long w0 = pack2(wv.x, wv.x);
        unsigned long long w1 = pack2(wv.y, wv.y);
        unsigned long long w2 = pack2(wv.z, wv.z);
        unsigned long long w3 = pack2(wv.w, wv.w);
        const ulonglong2* ar = reinterpret_cast<const ulonglong2*>(ab + k * ROWS);
        ulonglong2 a01 = ar[0];                   // broadcast LDS.128 rows 0..3
        ulonglong2 a23 = ar[1];                   // broadcast LDS.128 rows 4..7
        fma2(acc[0][0], a01.x, w0); fma2(acc[0][1], a01.y, w0);
        fma2(acc[0][2], a23.x, w0); fma2(acc[0][3], a23.y, w0);
        fma2(acc[1][0], a01.x, w1); fma2(acc[1][1], a01.y, w1);
        fma2(acc[1][2], a23.x, w1); fma2(acc[1][3], a23.y, w1);
        fma2(acc[2][0], a01.x, w2); fma2(acc[2][1], a01.y, w2);
        fma2(acc[2][2], a23.x, w2); fma2(acc[2][3], a23.y, w2);
        fma2(acc[3][0], a01.x, w3); fma2(acc[3][1], a01.y, w3);
        fma2(acc[3][2], a23.x, w3); fma2(acc[3][3], a23.y, w3);
    }

    if (q > 0) {
        // partial layout: [idx][q-1][t] -> consecutive t = conflict-free
#pragma unroll
        for (int c = 0; c < 4; c++)
#pragma unroll
            for (int i = 0; i < 4; i++)
                partial[(c * 4 + i) * 192 + (q - 1) * 64 + t] = acc[c][i];
    }
    __syncthreads();
    if (q == 0) {
#pragma unroll
        for (int c = 0; c < 4; c++) {
#pragma unroll
            for (int i = 0; i < 4; i++) {
                unsigned long long v = acc[c][i];
                int idx = c * 4 + i;
                v = add2(v, partial[idx * 192 +   0 + t]);
                v = add2(v, partial[idx * 192 +  64 + t]);
                v = add2(v, partial[idx * 192 + 128 + t]);
                float lo, hi;
                unpack2(v, lo, hi);
                *reinterpret_cast<unsigned long long*>(nxt + (n0 + c) * ROWS + 2 * i) =
                    pack2(fmaxf(lo, 0.0f), fmaxf(hi, 0.0f));
            }
        }
    }
}

__global__ void __launch_bounds__(NTHREADS, 3) lv_step_kernel(
    const float* __restrict__ W0, const float* __restrict__ b0,
    const float* __restrict__ W1, const float* __restrict__ b1,
    const float* __restrict__ W2, const float* __restrict__ b2,
    const float* __restrict__ W3, const float* __restrict__ b3,
    const float* __restrict__ obs_init, const float* __restrict__ feature_init,
    const float* __restrict__ tn_store, const float* __restrict__ x1_store,
    const float* __restrict__ x2_store, const float* __restrict__ path_seed,
    float* __restrict__ out, int s) {
    __shared__ __align__(16) float actA[HH * ROWS];
    __shared__ __align__(16) float actB[HH * ROWS];
    __shared__ __align__(16) unsigned long long partial_sh[16 * 3 * 64];
    __shared__ float inp_sh[ROWS][8];
    __shared__ float w3_sh[HH * 5];
    __shared__ float b3_sh[5];

    const int tid = threadIdx.x;
    const int row0 = blockIdx.x * ROWS;

    // stage W3/b3 into shared
    for (int i = tid; i < HH * 5; i += NTHREADS) w3_sh[i] = W3[i];
    if (tid < 5) b3_sh[tid] = b3[tid];

    // stage state (2 dims per particle) — warp 0
    if (tid < ROWS * 2) {
        int r = tid >> 1, d = tid & 1;
        int p = row0 + r;
        inp_sh[r][d] = (s == 0) ? obs_init[p * 2 + d] : g_state[p * 2 + d];
    }
    // stage features — warp 2
    if (s == 0) {
        if (tid >= 64 && tid < 64 + ROWS * 6) {
            int qq = tid - 64;
            int r = qq / 6, k = qq % 6;
            inp_sh[r][2 + k] = feature_init[(row0 + r) * 6 + k];
        }
    } else {
        if (tid == 64) {
            // replicate the reference's sequential fp32 time accumulation exactly
            float tt = feature_init[0];
            for (int j = 0; j < s; j++) tt += DTC;
            int i = s - 1;
            float f1 = tn_store[i], f2 = x1_store[i], f3 = x2_store[i];
#pragma unroll
            for (int r = 0; r < ROWS; r++) {
                inp_sh[r][2] = tt; inp_sh[r][3] = f1; inp_sh[r][4] = f2;
                inp_sh[r][5] = f3; inp_sh[r][6] = f2; inp_sh[r][7] = f3;
            }
        }
    }
    __syncthreads();

    // layer 0: (rows x 8) @ (8 x 256) + relu -> actA[n][r], 1 col per thread
    {
        const int n = tid;
        float w0c[8];
#pragma unroll
        for (int k = 0; k < 8; k++) w0c[k] = __ldg(W0 + k * HH + n);
        float bb = __ldg(b0 + n);
#pragma unroll
        for (int r = 0; r < ROWS; r++) {
            float a = bb;
#pragma unroll
            for (int k = 0; k < 8; k++) a = fmaf(inp_sh[r][k], w0c[k], a);
            actA[n * ROWS + r] = fmaxf(a, 0.0f);
        }
    }
    __syncthreads();

    mlp_layer(actA, actB, W1, b1, partial_sh, tid);
    __syncthreads();
    mlp_layer(actB, actA, W2, b2, partial_sh, tid);
    __syncthreads();

    // layer 3: (rows x 256) @ (256 x 5); one warp per row, 32-way split-K
    const int r = tid >> 5;
    const int lane = tid & 31;
    float acc5[5] = {0.f, 0.f, 0.f, 0.f, 0.f};
#pragma unroll
    for (int kk = 0; kk < 8; kk++) {
        int k = lane + (kk << 5);
        float a = actA[k * ROWS + r];
#pragma unroll
        for (int m = 0; m < 5; m++) acc5[m] = fmaf(a, w3_sh[k * 5 + m], acc5[m]);
    }
#pragma unroll
    for (int off = 16; off >= 1; off >>= 1) {
#pragma unroll
        for (int m = 0; m < 5; m++)
            acc5[m] += __shfl_down_sync(0xffffffffu, acc5[m], off);
    }

    if (lane == 0) {
        int p = row0 + r;
        float mu0 = acc5[0] + b3_sh[0];
        float mu1 = acc5[1] + b3_sh[1];
        float s11 = softplusf(acc5[2] + b3_sh[2]);
        float s21 = acc5[3] + b3_sh[3];
        float s22 = softplusf(acc5[4] + b3_sh[4]);
        float st0 = inp_sh[r][0], st1 = inp_sh[r][1];
        float e0 = path_seed[s * PP * 2 + p * 2 + 0];
        float e1 = path_seed[s * PP * 2 + p * 2 + 1];
        float n0 = softplusf(st0 + DTC * mu0 + SQRT_DTC * (s11 * e0));
        float n1 = softplusf(st1 + DTC * mu1 + SQRT_DTC * (s21 * e0 + s22 * e1));
        g_state[p * 2 + 0] = n0;
        g_state[p * 2 + 1] = n1;

        // path: out[p*202 + d*101 + t]; step s writes t = s+1
        out[p * 202 + (s + 1)]       = n0;
        out[p * 202 + 101 + (s + 1)] = n1;
        if (s == 0) {  // t = 0 comes from obs_init
            out[p * 202 + 0]   = st0;
            out[p * 202 + 101] = st1;
        }
        // mu_store: base P*202, [(p*100 + s)*2 + d]
        int mb = PP * 202 + (p * 100 + s) * 2;
        out[mb + 0] = mu0;
        out[mb + 1] = mu1;
        // sigma_store: base P*202 + P*200, [(p*100 + s)*4 + i*2 + j]
        int sb = PP * 202 + PP * 200 + (p * 100 + s) * 4;
        out[sb + 0] = s11;
        out[sb + 1] = 0.0f;   // chol[0][1]
        out[sb + 2] = s21;
        out[sb + 3] = s22;
    }
}

extern "C" void kernel_launch(void* const* d_in, const int* in_sizes, int n_in,
                              void* d_out, int out_size) {
    const float* W0 = (const float*)d_in[0];
    const float* b0 = (const float*)d_in[1];
    const float* W1 = (const float*)d_in[2];
    const float* b1 = (const float*)d_in[3];
    const float* W2 = (const float*)d_in[4];
    const float* b2 = (const float*)d_in[5];
    const float* W3 = (const float*)d_in[6];
    const float* b3 = (const float*)d_in[7];
    const float* obs_init = (const float*)d_in[8];
    const float* feature_init = (const float*)d_in[9];
    const float* tn_store = (const float*)d_in[10];
    const float* x1_store = (const float*)d_in[11];
    const float* x2_store = (const float*)d_in[12];
    const float* path_seed = (const float*)d_in[13];
    float* out = (float*)d_out;

    dim3 grid(NBLOCKS);   // 512 blocks
    dim3 block(NTHREADS);
    for (int s = 0; s < NSTEPS; s++) {
        lv_step_kernel<<<grid, block>>>(W0, b0, W1, b1, W2, b2, W3, b3,
                                        obs_init, feature_init, tn_store,
                                        x1_store, x2_store, path_seed, out, s);
    }
}

// round 4
// speedup vs baseline: 1.1899x; 1.1899x over previous
#include <cuda_runtime.h>

#define PP        4096
#define HH        256
#define NSTEPS    100
#define DTC       0.1f
#define SQRT_DTC  0.31622776601683794f
#define ROWS      16
#define RS        20            // padded act row stride (floats); 80B, 16B-aligned
#define NTHREADS  256           // 128 col-threads (2 cols each) x 2 k-halves
#define NBLOCKS   (PP / ROWS)   // 256

#define ACT_FLOATS (HH * RS)    // 5120 floats = 20480 B
// dynamic smem: actA + actB + partial(16*128 ull) + w3 + inp + b3 + t
#define SMEM_BYTES (ACT_FLOATS*4*2 + 16*128*8 + HH*5*4 + ROWS*8*4 + 8*4)

__device__ __forceinline__ float softplusf(float x) {
    // matches jax.nn.softplus == max(x,0) + log1p(exp(-|x|))
    return fmaxf(x, 0.0f) + log1pf(expf(-fabsf(x)));
}

__device__ __forceinline__ unsigned long long pack2(float lo, float hi) {
    unsigned long long r;
    asm("mov.b64 %0, {%1, %2};" : "=l"(r) : "f"(lo), "f"(hi));
    return r;
}
__device__ __forceinline__ void unpack2(unsigned long long v, float& lo, float& hi) {
    asm("mov.b64 {%0, %1}, %2;" : "=f"(lo), "=f"(hi) : "l"(v));
}
__device__ __forceinline__ void fma2(unsigned long long& d, unsigned long long a,
                                     unsigned long long b) {
    asm("fma.rn.f32x2 %0, %1, %2, %0;" : "+l"(d) : "l"(a), "l"(b));
}
__device__ __forceinline__ unsigned long long add2(unsigned long long a,
                                                   unsigned long long b) {
    unsigned long long r;
    asm("add.rn.f32x2 %0, %1, %2;" : "=l"(r) : "l"(a), "l"(b));
    return r;
}

// One 256->256 layer + relu. act/nxt layout: [col][row], row stride RS, 16 rows.
// Thread (t = tid&127, q = tid>>7): output cols 2t, 2t+1; k-half [128q,128q+128).
// Per k: 1 LDG.64 (2 weights) + 4 broadcast LDS.128 + 16 FFMA2.
__device__ __forceinline__ void mlp_layer(const float* act, float* nxt,
                                          const float2* __restrict__ wp,
                                          const float* __restrict__ b,
                                          unsigned long long* partial,
                                          int t, int q) {
    const int n0 = 2 * t;
    unsigned long long accA[8], accB[8];
    if (q == 0) {
        float2 bv = __ldg(reinterpret_cast<const float2*>(b) + t);
#pragma unroll
        for (int i = 0; i < 8; i++) { accA[i] = pack2(bv.x, bv.x); accB[i] = pack2(bv.y, bv.y); }
    } else {
#pragma unroll
        for (int i = 0; i < 8; i++) { accA[i] = 0ull; accB[i] = 0ull; }
    }

    const float* ab = act + q * 128 * RS;
#pragma unroll 4
    for (int k = 0; k < 128; k++) {
        float2 w = __ldg(wp + k * (HH / 2));      // coalesced, L2-resident
        unsigned long long w0 = pack2(w.x, w.x);
        unsigned long long w1 = pack2(w.y, w.y);
        const ulonglong2* ar = reinterpret_cast<const ulonglong2*>(ab + k * RS);
        ulonglong2 a0 = ar[0], a1 = ar[1], a2 = ar[2], a3 = ar[3]; // 16 rows, broadcast
        fma2(accA[0], a0.x, w0); fma2(accA[1], a0.y, w0);
        fma2(accA[2], a1.x, w0); fma2(accA[3], a1.y, w0);
        fma2(accA[4], a2.x, w0); fma2(accA[5], a2.y, w0);
        fma2(accA[6], a3.x, w0); fma2(accA[7], a3.y, w0);
        fma2(accB[0], a0.x, w1); fma2(accB[1], a0.y, w1);
        fma2(accB[2], a1.x, w1); fma2(accB[3], a1.y, w1);
        fma2(accB[4], a2.x, w1); fma2(accB[5], a2.y, w1);
        fma2(accB[6], a3.x, w1); fma2(accB[7], a3.y, w1);
    }

    if (q) {
#pragma unroll
        for (int i = 0; i < 8; i++) {
            partial[i * 128 + t]       = accA[i];
            partial[(8 + i) * 128 + t] = accB[i];
        }
    }
    __syncthreads();
    if (!q) {
#pragma unroll
        for (int i = 0; i < 8; i++) {
            unsigned long long v = add2(accA[i], partial[i * 128 + t]);
            float lo, hi; unpack2(v, lo, hi);
            *reinterpret_cast<unsigned long long*>(nxt + n0 * RS + 2 * i) =
                pack2(fmaxf(lo, 0.0f), fmaxf(hi, 0.0f));
            v = add2(accB[i], partial[(8 + i) * 128 + t]);
            unpack2(v, lo, hi);
            *reinterpret_cast<unsigned long long*>(nxt + (n0 + 1) * RS + 2 * i) =
                pack2(fmaxf(lo, 0.0f), fmaxf(hi, 0.0f));
        }
    }
}

__global__ void __launch_bounds__(NTHREADS, 2) lv_kernel(
    const float* __restrict__ W0, const float* __restrict__ b0,
    const float* __restrict__ W1, const float* __restrict__ b1,
    const float* __restrict__ W2, const float* __restrict__ b2,
    const float* __restrict__ W3, const float* __restrict__ b3,
    const float* __restrict__ obs_init, const float* __restrict__ feature_init,
    const float* __restrict__ tn_store, const float* __restrict__ x1_store,
    const float* __restrict__ x2_store, const float* __restrict__ path_seed,
    float* __restrict__ out) {
    extern __shared__ __align__(16) unsigned char smem_raw[];
    float* actA = reinterpret_cast<float*>(smem_raw);
    float* actB = actA + ACT_FLOATS;
    unsigned long long* partial = reinterpret_cast<unsigned long long*>(actB + ACT_FLOATS);
    float* w3_sh  = reinterpret_cast<float*>(partial + 16 * 128);
    float* inp_sh = w3_sh + HH * 5;          // [r*8 + k], 16x8
    float* b3_sh  = inp_sh + ROWS * 8;
    float* t_sh   = b3_sh + 5;

    const int tid  = threadIdx.x;
    const int row0 = blockIdx.x * ROWS;
    const int t    = tid & 127;
    const int q    = tid >> 7;

    // ---- one-time staging ----
    for (int i = tid; i < HH * 5; i += NTHREADS) w3_sh[i] = W3[i];
    if (tid < 5) b3_sh[tid] = b3[tid];
    if (tid == 0) *t_sh = feature_init[0];
    if (tid < ROWS * 2) {
        int r = tid >> 1, d = tid & 1;
        inp_sh[r * 8 + d] = obs_init[(row0 + r) * 2 + d];
    }
    if (tid < ROWS * 6) {   // s=0 features are per-particle
        int r = tid / 6, k = tid % 6;
        inp_sh[r * 8 + 2 + k] = feature_init[(row0 + r) * 6 + k];
    }

    // W0 column + b0 live in registers for the whole trajectory
    float w0c[8];
#pragma unroll
    for (int k = 0; k < 8; k++) w0c[k] = __ldg(W0 + k * HH + tid);
    const float b0v = __ldg(b0 + tid);

    const float2* wp1 = reinterpret_cast<const float2*>(W1 + q * 128 * HH) + t;
    const float2* wp2 = reinterpret_cast<const float2*>(W2 + q * 128 * HH) + t;

    // layer-3 mapping: warp w -> rows 2w, 2w+1 (half-warp each), 16-way split-K
    const int warp = tid >> 5, lane = tid & 31;
    const int l3r = 2 * warp + (lane >> 4);
    const int l3l = lane & 15;

#pragma unroll 1
    for (int s = 0; s < NSTEPS; s++) {
        if (s > 0) {
            if (tid == 0) *t_sh += DTC;   // exact sequential fp32 accumulation
            __syncthreads();
            if (tid < ROWS * 6) {
                int r = tid / 6, k = tid % 6;
                int i = s - 1;
                float f;
                if      (k == 0) f = *t_sh;
                else if (k == 1) f = __ldg(tn_store + i);
                else if (k == 2 || k == 4) f = __ldg(x1_store + i);
                else             f = __ldg(x2_store + i);
                inp_sh[r * 8 + 2 + k] = f;
            }
        }
        __syncthreads();

        // layer 0: (16 x 8) @ (8 x 256) + relu -> actA[n][r], col n = tid
#pragma unroll
        for (int r = 0; r < ROWS; r++) {
            float a = b0v;
#pragma unroll
            for (int k = 0; k < 8; k++) a = fmaf(inp_sh[r * 8 + k], w0c[k], a);
            actA[tid * RS + r] = fmaxf(a, 0.0f);
        }
        __syncthreads();

        mlp_layer(actA, actB, wp1, b1, partial, t, q);
        __syncthreads();
        mlp_layer(actB, actA, wp2, b2, partial, t, q);
        __syncthreads();

        // layer 3: (16 x 256) @ (256 x 5), half-warp per row, 16-way split-K
        float acc5[5] = {0.f, 0.f, 0.f, 0.f, 0.f};
#pragma unroll
        for (int kk = 0; kk < 16; kk++) {
            int k = l3l + (kk << 4);
            float a = actA[k * RS + l3r];
#pragma unroll
            for (int m = 0; m < 5; m++) acc5[m] = fmaf(a, w3_sh[k * 5 + m], acc5[m]);
        }
#pragma unroll
        for (int off = 8; off >= 1; off >>= 1) {
#pragma unroll
            for (int m = 0; m < 5; m++)
                acc5[m] += __shfl_down_sync(0xffffffffu, acc5[m], off, 16);
        }

        if (l3l == 0) {
            const int r = l3r;
            const int p = row0 + r;
            float mu0 = acc5[0] + b3_sh[0];
            float mu1 = acc5[1] + b3_sh[1];
            float s11 = softplusf(acc5[2] + b3_sh[2]);
            float s21 = acc5[3] + b3_sh[3];
            float s22 = softplusf(acc5[4] + b3_sh[4]);
            float st0 = inp_sh[r * 8 + 0], st1 = inp_sh[r * 8 + 1];
            float2 e = __ldg(reinterpret_cast<const float2*>(path_seed) + s * PP + p);
            float n0v = softplusf(st0 + DTC * mu0 + SQRT_DTC * (s11 * e.x));
            float n1v = softplusf(st1 + DTC * mu1 + SQRT_DTC * (s21 * e.x + s22 * e.y));
            inp_sh[r * 8 + 0] = n0v;   // carried state
            inp_sh[r * 8 + 1] = n1v;

            // path: out[p*202 + d*101 + time]; step s writes time = s+1
            out[p * 202 + (s + 1)]       = n0v;
            out[p * 202 + 101 + (s + 1)] = n1v;
            if (s == 0) {
                out[p * 202 + 0]   = st0;
                out[p * 202 + 101] = st1;
            }
            int mb = PP * 202 + (p * 100 + s) * 2;
            out[mb + 0] = mu0;
            out[mb + 1] = mu1;
            int sb = PP * 202 + PP * 200 + (p * 100 + s) * 4;
            out[sb + 0] = s11;
            out[sb + 1] = 0.0f;
            out[sb + 2] = s21;
            out[sb + 3] = s22;
        }
        __syncthreads();
    }
}

extern "C" void kernel_launch(void* const* d_in, const int* in_sizes, int n_in,
                              void* d_out, int out_size) {
    const float* W0 = (const float*)d_in[0];
    const float* b0 = (const float*)d_in[1];
    const float* W1 = (const float*)d_in[2];
    const float* b1 = (const float*)d_in[3];
    const float* W2 = (const float*)d_in[4];
    const float* b2 = (const float*)d_in[5];
    const float* W3 = (const float*)d_in[6];
    const float* b3 = (const float*)d_in[7];
    const float* obs_init = (const float*)d_in[8];
    const float* feature_init = (const float*)d_in[9];
    const float* tn_store = (const float*)d_in[10];
    const float* x1_store = (const float*)d_in[11];
    const float* x2_store = (const float*)d_in[12];
    const float* path_seed = (const float*)d_in[13];
    float* out = (float*)d_out;

    cudaFuncSetAttribute(lv_kernel, cudaFuncAttributeMaxDynamicSharedMemorySize,
                         SMEM_BYTES);
    lv_kernel<<<NBLOCKS, NTHREADS, SMEM_BYTES>>>(
        W0, b0, W1, b1, W2, b2, W3, b3, obs_init, feature_init,
        tn_store, x1_store, x2_store, path_seed, out);
}

// round 5
// speedup vs baseline: 1.3613x; 1.1440x over previous
#include <cuda_runtime.h>

#define PP        4096
#define HH        256
#define NSTEPS    100
#define DTC       0.1f
#define SQRT_DTC  0.31622776601683794f
#define ROWS      16
#define RS        20            // padded act row stride (floats)
#define NTHREADS  256           // 64 col-threads (4 cols each) x 4 k-quarters
#define NBLOCKS   (PP / ROWS)   // 256

// dynamic smem layout (bytes):
// actA 20480 | actB 20480 | partial 32768 | w0 8192 | w3 5120 | b0/b1/b2 3072
// b3 32 | st 128 | inp0 512   => 90784 B  (2 CTAs/SM = 181568 B, fits)
#define SMEM_BYTES 90784

typedef unsigned long long ull;

__device__ __forceinline__ float softplusf(float x) {
    return fmaxf(x, 0.0f) + log1pf(expf(-fabsf(x)));
}
__device__ __forceinline__ ull pack2(float lo, float hi) {
    ull r; asm("mov.b64 %0, {%1, %2};" : "=l"(r) : "f"(lo), "f"(hi)); return r;
}
__device__ __forceinline__ void unpack2(ull v, float& lo, float& hi) {
    asm("mov.b64 {%0, %1}, %2;" : "=f"(lo), "=f"(hi) : "l"(v));
}
__device__ __forceinline__ void fma2(ull& d, ull a, ull b) {
    asm("fma.rn.f32x2 %0, %1, %2, %0;" : "+l"(d) : "l"(a), "l"(b));
}
__device__ __forceinline__ ull add2(ull a, ull b) {
    ull r; asm("add.rn.f32x2 %0, %1, %2;" : "=l"(r) : "l"(a), "l"(b)); return r;
}

// One 256->256 layer + relu. act/nxt: [col][row], stride RS, 16 rows.
// Thread (t = tid&63, q = tid>>6): cols 4t..4t+3, k-quarter [64q, 64q+64).
// Per k: 1 LDG.128 + 4 broadcast LDS.128 + 32 FFMA2.
// Reduction: all quarters dump to partial; thread (q,t) reduces col 4t+q.
// Two phases of 16 accs each keep the partial buffer at 32KB.
__device__ __forceinline__ void mlp_layer(const float* act, float* nxt,
                                          const float4* __restrict__ wp,
                                          const float* b_sh, ull* partial,
                                          int t, int q) {
    ull acc[4][8];
#pragma unroll
    for (int c = 0; c < 4; c++)
#pragma unroll
        for (int i = 0; i < 8; i++) acc[c][i] = 0ull;

    const float* ab = act + q * 64 * RS;
#pragma unroll 4
    for (int k = 0; k < 64; k++) {
        float4 wv = __ldg(wp + k * (HH / 4));
        ull w0 = pack2(wv.x, wv.x);
        ull w1 = pack2(wv.y, wv.y);
        ull w2 = pack2(wv.z, wv.z);
        ull w3 = pack2(wv.w, wv.w);
        const ulonglong2* ar = reinterpret_cast<const ulonglong2*>(ab + k * RS);
        ulonglong2 a0 = ar[0], a1 = ar[1], a2 = ar[2], a3 = ar[3];
        fma2(acc[0][0], a0.x, w0); fma2(acc[0][1], a0.y, w0);
        fma2(acc[0][2], a1.x, w0); fma2(acc[0][3], a1.y, w0);
        fma2(acc[0][4], a2.x, w0); fma2(acc[0][5], a2.y, w0);
        fma2(acc[0][6], a3.x, w0); fma2(acc[0][7], a3.y, w0);
        fma2(acc[1][0], a0.x, w1); fma2(acc[1][1], a0.y, w1);
        fma2(acc[1][2], a1.x, w1); fma2(acc[1][3], a1.y, w1);
        fma2(acc[1][4], a2.x, w1); fma2(acc[1][5], a2.y, w1);
        fma2(acc[1][6], a3.x, w1); fma2(acc[1][7], a3.y, w1);
        fma2(acc[2][0], a0.x, w2); fma2(acc[2][1], a0.y, w2);
        fma2(acc[2][2], a1.x, w2); fma2(acc[2][3], a1.y, w2);
        fma2(acc[2][4], a2.x, w2); fma2(acc[2][5], a2.y, w2);
        fma2(acc[2][6], a3.x, w2); fma2(acc[2][7], a3.y, w2);
        fma2(acc[3][0], a0.x, w3); fma2(acc[3][1], a0.y, w3);
        fma2(acc[3][2], a1.x, w3); fma2(acc[3][3], a1.y, w3);
        fma2(acc[3][4], a2.x, w3); fma2(acc[3][5], a2.y, w3);
        fma2(acc[3][6], a3.x, w3); fma2(acc[3][7], a3.y, w3);
    }

    const int bq = q * 64 + t;
    const int col = 4 * t + q;
    const float bb = b_sh[col];
#pragma unroll
    for (int ph = 0; ph < 2; ph++) {
#pragma unroll
        for (int c = 0; c < 4; c++)
#pragma unroll
            for (int j = 0; j < 4; j++)
                partial[((c * 4 + j) << 8) + bq] = acc[c][ph * 4 + j];
        __syncthreads();
#pragma unroll
        for (int j = 0; j < 4; j++) {
            const int slot = ((q * 4 + j) << 8) + t;
            ull v = add2(partial[slot], partial[slot + 64]);
            v = add2(v, add2(partial[slot + 128], partial[slot + 192]));
            float lo, hi; unpack2(v, lo, hi);
            lo = fmaxf(lo + bb, 0.0f);
            hi = fmaxf(hi + bb, 0.0f);
            *reinterpret_cast<ull*>(nxt + col * RS + 2 * (ph * 4 + j)) = pack2(lo, hi);
        }
        __syncthreads();
    }
}

__global__ void __launch_bounds__(NTHREADS, 2) lv_kernel(
    const float* __restrict__ W0, const float* __restrict__ b0,
    const float* __restrict__ W1, const float* __restrict__ b1,
    const float* __restrict__ W2, const float* __restrict__ b2,
    const float* __restrict__ W3, const float* __restrict__ b3,
    const float* __restrict__ obs_init, const float* __restrict__ feature_init,
    const float* __restrict__ tn_store, const float* __restrict__ x1_store,
    const float* __restrict__ x2_store, const float* __restrict__ path_seed,
    float* __restrict__ out) {
    extern __shared__ __align__(16) unsigned char smem_raw[];
    float* actA = reinterpret_cast<float*>(smem_raw);                 // 5120 f
    float* actB = actA + HH * RS;                                     // 5120 f
    ull*   partial = reinterpret_cast<ull*>(actB + HH * RS);          // 4096 ull
    float* w0_sh = reinterpret_cast<float*>(partial + 4096);          // 2048 f
    float* w3_sh = w0_sh + 8 * HH;                                    // 1280 f
    float* b0_sh = w3_sh + HH * 5;                                    // 256 f
    float* b1_sh = b0_sh + HH;                                        // 256 f
    float* b2_sh = b1_sh + HH;                                        // 256 f
    float* b3_sh = b2_sh + HH;                                        // 8 f
    float* st_sh = b3_sh + 8;                                         // 32 f
    float* inp0_sh = st_sh + 32;                                      // 128 f

    const int tid  = threadIdx.x;
    const int row0 = blockIdx.x * ROWS;
    const int t    = tid & 63;
    const int q    = tid >> 6;

    // ---- one-time staging ----
    for (int i = tid; i < 8 * HH; i += NTHREADS) w0_sh[i] = W0[i];
    for (int i = tid; i < HH * 5; i += NTHREADS) w3_sh[i] = W3[i];
    if (tid < HH) { b0_sh[tid] = b0[tid]; b1_sh[tid] = b1[tid]; b2_sh[tid] = b2[tid]; }
    if (tid < 5) b3_sh[tid] = b3[tid];
    if (tid < ROWS * 2) st_sh[tid] = obs_init[row0 * 2 + tid];
    if (tid < ROWS * 8) {
        int r = tid >> 3, k = tid & 7;
        inp0_sh[tid] = (k < 2) ? obs_init[(row0 + r) * 2 + k]
                               : feature_init[(row0 + r) * 6 + (k - 2)];
    }
    float t_reg = __ldg(feature_init);   // t0 = feature_init[0,0,0]
    __syncthreads();

    const float4* wp1 = reinterpret_cast<const float4*>(W1) + q * 64 * (HH / 4) + t;
    const float4* wp2 = reinterpret_cast<const float4*>(W2) + q * 64 * (HH / 4) + t;

    // layer-3 mapping: warp w -> rows 2w, 2w+1 (half-warp each), 16-way split-K
    const int warp = tid >> 5, lane = tid & 31;
    const int l3r = 2 * warp + (lane >> 4);
    const int l3l = lane & 15;

#pragma unroll 1
    for (int s = 0; s < NSTEPS; s++) {
        // ---- layer 0: (16 x 8) @ (8 x 256) + relu -> actA[n][r], col n = tid
        if (s == 0) {
            float a;
#pragma unroll
            for (int r = 0; r < ROWS; r++) {
                a = b0_sh[tid];
#pragma unroll
                for (int k = 0; k < 8; k++)
                    a = fmaf(inp0_sh[r * 8 + k], w0_sh[k * HH + tid], a);
                actA[tid * RS + r] = fmaxf(a, 0.0f);
            }
        } else {
            t_reg += DTC;   // exact sequential fp32 accumulation
            const int i = s - 1;
            const float f_tn = __ldg(tn_store + i);
            const float f_x1 = __ldg(x1_store + i);
            const float f_x2 = __ldg(x2_store + i);
            // features are row-uniform: fold them once
            float base = b0_sh[tid];
            base = fmaf(t_reg, w0_sh[2 * HH + tid], base);
            base = fmaf(f_tn,  w0_sh[3 * HH + tid], base);
            base = fmaf(f_x1,  w0_sh[4 * HH + tid], base);
            base = fmaf(f_x2,  w0_sh[5 * HH + tid], base);
            base = fmaf(f_x1,  w0_sh[6 * HH + tid], base);
            base = fmaf(f_x2,  w0_sh[7 * HH + tid], base);
            const float wa = w0_sh[tid], wb = w0_sh[HH + tid];
#pragma unroll
            for (int r = 0; r < ROWS; r++) {
                float a = fmaf(st_sh[2 * r], wa, fmaf(st_sh[2 * r + 1], wb, base));
                actA[tid * RS + r] = fmaxf(a, 0.0f);
            }
        }
        __syncthreads();

        mlp_layer(actA, actB, wp1, b1_sh, partial, t, q);
        mlp_layer(actB, actA, wp2, b2_sh, partial, t, q);

        // ---- layer 3: (16 x 256) @ (256 x 5), half-warp per row, 16-way split-K
        float acc5[5] = {0.f, 0.f, 0.f, 0.f, 0.f};
#pragma unroll
        for (int kk = 0; kk < 16; kk++) {
            int k = l3l + (kk << 4);
            float a = actA[k * RS + l3r];
#pragma unroll
            for (int m = 0; m < 5; m++) acc5[m] = fmaf(a, w3_sh[k * 5 + m], acc5[m]);
        }
#pragma unroll
        for (int off = 8; off >= 1; off >>= 1) {
#pragma unroll
            for (int m = 0; m < 5; m++)
                acc5[m] += __shfl_down_sync(0xffffffffu, acc5[m], off, 16);
        }

        if (l3l == 0) {
            const int r = l3r;
            const int p = row0 + r;
            float mu0 = acc5[0] + b3_sh[0];
            float mu1 = acc5[1] + b3_sh[1];
            float s11 = softplusf(acc5[2] + b3_sh[2]);
            float s21 = acc5[3] + b3_sh[3];
            float s22 = softplusf(acc5[4] + b3_sh[4]);
            float st0 = st_sh[2 * r], st1 = st_sh[2 * r + 1];
            float2 e = __ldg(reinterpret_cast<const float2*>(path_seed) + s * PP + p);
            float n0v = softplusf(st0 + DTC * mu0 + SQRT_DTC * (s11 * e.x));
            float n1v = softplusf(st1 + DTC * mu1 + SQRT_DTC * (s21 * e.x + s22 * e.y));
            st_sh[2 * r]     = n0v;
            st_sh[2 * r + 1] = n1v;

            // path: out[p*202 + d*101 + time]; step s writes time = s+1
            out[p * 202 + (s + 1)]       = n0v;
            out[p * 202 + 101 + (s + 1)] = n1v;
            if (s == 0) {
                out[p * 202 + 0]   = st0;
                out[p * 202 + 101] = st1;
            }
            int mb = PP * 202 + (p * 100 + s) * 2;
            out[mb + 0] = mu0;
            out[mb + 1] = mu1;
            int sb = PP * 202 + PP * 200 + (p * 100 + s) * 4;
            out[sb + 0] = s11;
            out[sb + 1] = 0.0f;
            out[sb + 2] = s21;
            out[sb + 3] = s22;
        }
        __syncthreads();
    }
}

extern "C" void kernel_launch(void* const* d_in, const int* in_sizes, int n_in,
                              void* d_out, int out_size) {
    const float* W0 = (const float*)d_in[0];
    const float* b0 = (const float*)d_in[1];
    const float* W1 = (const float*)d_in[2];
    const float* b1 = (const float*)d_in[3];
    const float* W2 = (const float*)d_in[4];
    const float* b2 = (const float*)d_in[5];
    const float* W3 = (const float*)d_in[6];
    const float* b3 = (const float*)d_in[7];
    const float* obs_init = (const float*)d_in[8];
    const float* feature_init = (const float*)d_in[9];
    const float* tn_store = (const float*)d_in[10];
    const float* x1_store = (const float*)d_in[11];
    const float* x2_store = (const float*)d_in[12];
    const float* path_seed = (const float*)d_in[13];
    float* out = (float*)d_out;

    cudaFuncSetAttribute(lv_kernel, cudaFuncAttributeMaxDynamicSharedMemorySize,
                         SMEM_BYTES);
    lv_kernel<<<NBLOCKS, NTHREADS, SMEM_BYTES>>>(
        W0, b0, W1, b1, W2, b2, W3, b3, obs_init, feature_init,
        tn_store, x1_store, x2_store, path_seed, out);
}

// round 6
// speedup vs baseline: 1.3714x; 1.0074x over previous
#include <cuda_runtime.h>

#define PP        4096
#define HH        256
#define NSTEPS    100
#define DTC       0.1f
#define SQRT_DTC  0.31622776601683794f
#define ROWS      16
#define RS        20            // padded act row stride (floats)
#define NTHREADS  256           // 64 col-threads (4 cols each) x 4 k-quarters
#define NBLOCKS   (PP / ROWS)   // 256

// dynamic smem layout (bytes):
// actA 20480 | actB 20480 | partial 32768 | w0 8192 | w3 5120 | b0/b1/b2 3072
// b3 32 | st 128 | inp0 512   => 90784 B  (2 CTAs/SM = 181568 B, fits)
#define SMEM_BYTES 90784

typedef unsigned long long ull;

__device__ __forceinline__ float softplusf(float x) {
    return fmaxf(x, 0.0f) + log1pf(expf(-fabsf(x)));
}
__device__ __forceinline__ ull pack2(float lo, float hi) {
    ull r; asm("mov.b64 %0, {%1, %2};" : "=l"(r) : "f"(lo), "f"(hi)); return r;
}
__device__ __forceinline__ void unpack2(ull v, float& lo, float& hi) {
    asm("mov.b64 {%0, %1}, %2;" : "=f"(lo), "=f"(hi) : "l"(v));
}
__device__ __forceinline__ void fma2(ull& d, ull a, ull b) {
    asm("fma.rn.f32x2 %0, %1, %2, %0;" : "+l"(d) : "l"(a), "l"(b));
}
__device__ __forceinline__ ull add2(ull a, ull b) {
    ull r; asm("add.rn.f32x2 %0, %1, %2;" : "=l"(r) : "l"(a), "l"(b)); return r;
}

// One 256->256 layer + relu. act/nxt: [col][row], stride RS, 16 rows.
// Thread (t = tid&63, q = tid>>6): cols 4t..4t+3, k-quarter [64q, 64q+64).
// Per k: 1 LDG.128 + 4 broadcast LDS.128 + 32 FFMA2.
// Reduction: all quarters dump to partial; thread (q,t) reduces col 4t+q.
// Two phases of 16 accs each keep the partial buffer at 32KB.
__device__ __forceinline__ void mlp_layer(const float* act, float* nxt,
                                          const float4* __restrict__ wp,
                                          const float* b_sh, ull* partial,
                                          int t, int q) {
    ull acc[4][8];
#pragma unroll
    for (int c = 0; c < 4; c++)
#pragma unroll
        for (int i = 0; i < 8; i++) acc[c][i] = 0ull;

    const float* ab = act + q * 64 * RS;
#pragma unroll 4
    for (int k = 0; k < 64; k++) {
        float4 wv = __ldg(wp + k * (HH / 4));
        ull w0 = pack2(wv.x, wv.x);
        ull w1 = pack2(wv.y, wv.y);
        ull w2 = pack2(wv.z, wv.z);
        ull w3 = pack2(wv.w, wv.w);
        const ulonglong2* ar = reinterpret_cast<const ulonglong2*>(ab + k * RS);
        ulonglong2 a0 = ar[0], a1 = ar[1], a2 = ar[2], a3 = ar[3];
        fma2(acc[0][0], a0.x, w0); fma2(acc[0][1], a0.y, w0);
        fma2(acc[0][2], a1.x, w0); fma2(acc[0][3], a1.y, w0);
        fma2(acc[0][4], a2.x, w0); fma2(acc[0][5], a2.y, w0);
        fma2(acc[0][6], a3.x, w0); fma2(acc[0][7], a3.y, w0);
        fma2(acc[1][0], a0.x, w1); fma2(acc[1][1], a0.y, w1);
        fma2(acc[1][2], a1.x, w1); fma2(acc[1][3], a1.y, w1);
        fma2(acc[1][4], a2.x, w1); fma2(acc[1][5], a2.y, w1);
        fma2(acc[1][6], a3.x, w1); fma2(acc[1][7], a3.y, w1);
        fma2(acc[2][0], a0.x, w2); fma2(acc[2][1], a0.y, w2);
        fma2(acc[2][2], a1.x, w2); fma2(acc[2][3], a1.y, w2);
        fma2(acc[2][4], a2.x, w2); fma2(acc[2][5], a2.y, w2);
        fma2(acc[2][6], a3.x, w2); fma2(acc[2][7], a3.y, w2);
        fma2(acc[3][0], a0.x, w3); fma2(acc[3][1], a0.y, w3);
        fma2(acc[3][2], a1.x, w3); fma2(acc[3][3], a1.y, w3);
        fma2(acc[3][4], a2.x, w3); fma2(acc[3][5], a2.y, w3);
        fma2(acc[3][6], a3.x, w3); fma2(acc[3][7], a3.y, w3);
    }

    const int bq = q * 64 + t;
    const int col = 4 * t + q;
    const float bb = b_sh[col];
#pragma unroll
    for (int ph = 0; ph < 2; ph++) {
#pragma unroll
        for (int c = 0; c < 4; c++)
#pragma unroll
            for (int j = 0; j < 4; j++)
                partial[((c * 4 + j) << 8) + bq] = acc[c][ph * 4 + j];
        __syncthreads();
#pragma unroll
        for (int j = 0; j < 4; j++) {
            const int slot = ((q * 4 + j) << 8) + t;
            ull v = add2(partial[slot], partial[slot + 64]);
            v = add2(v, add2(partial[slot + 128], partial[slot + 192]));
            float lo, hi; unpack2(v, lo, hi);
            lo = fmaxf(lo + bb, 0.0f);
            hi = fmaxf(hi + bb, 0.0f);
            *reinterpret_cast<ull*>(nxt + col * RS + 2 * (ph * 4 + j)) = pack2(lo, hi);
        }
        __syncthreads();
    }
}

__global__ void __launch_bounds__(NTHREADS, 2) lv_kernel(
    const float* __restrict__ W0, const float* __restrict__ b0,
    const float* __restrict__ W1, const float* __restrict__ b1,
    const float* __restrict__ W2, const float* __restrict__ b2,
    const float* __restrict__ W3, const float* __restrict__ b3,
    const float* __restrict__ obs_init, const float* __restrict__ feature_init,
    const float* __restrict__ tn_store, const float* __restrict__ x1_store,
    const float* __restrict__ x2_store, const float* __restrict__ path_seed,
    float* __restrict__ out) {
    extern __shared__ __align__(16) unsigned char smem_raw[];
    float* actA = reinterpret_cast<float*>(smem_raw);                 // 5120 f
    float* actB = actA + HH * RS;                                     // 5120 f
    ull*   partial = reinterpret_cast<ull*>(actB + HH * RS);          // 4096 ull
    float* w0_sh = reinterpret_cast<float*>(partial + 4096);          // 2048 f
    float* w3_sh = w0_sh + 8 * HH;                                    // 1280 f
    float* b0_sh = w3_sh + HH * 5;                                    // 256 f
    float* b1_sh = b0_sh + HH;                                        // 256 f
    float* b2_sh = b1_sh + HH;                                        // 256 f
    float* b3_sh = b2_sh + HH;                                        // 8 f
    float* st_sh = b3_sh + 8;                                         // 32 f
    float* inp0_sh = st_sh + 32;                                      // 128 f

    const int tid  = threadIdx.x;
    const int row0 = blockIdx.x * ROWS;
    const int t    = tid & 63;
    const int q    = tid >> 6;

    // ---- one-time staging ----
    for (int i = tid; i < 8 * HH; i += NTHREADS) w0_sh[i] = W0[i];
    for (int i = tid; i < HH * 5; i += NTHREADS) w3_sh[i] = W3[i];
    if (tid < HH) { b0_sh[tid] = b0[tid]; b1_sh[tid] = b1[tid]; b2_sh[tid] = b2[tid]; }
    if (tid < 5) b3_sh[tid] = b3[tid];
    if (tid < ROWS * 2) st_sh[tid] = obs_init[row0 * 2 + tid];
    if (tid < ROWS * 8) {
        int r = tid >> 3, k = tid & 7;
        inp0_sh[tid] = (k < 2) ? obs_init[(row0 + r) * 2 + k]
                               : feature_init[(row0 + r) * 6 + (k - 2)];
    }
    float t_reg = __ldg(feature_init);   // t0 = feature_init[0,0,0]
    __syncthreads();

    const float4* wp1 = reinterpret_cast<const float4*>(W1) + q * 64 * (HH / 4) + t;
    const float4* wp2 = reinterpret_cast<const float4*>(W2) + q * 64 * (HH / 4) + t;

    // layer-3 mapping: warp w -> rows 2w, 2w+1 (half-warp each), 16-way split-K
    const int warp = tid >> 5, lane = tid & 31;
    const int l3r = 2 * warp + (lane >> 4);
    const int l3l = lane & 15;

#pragma unroll 1
    for (int s = 0; s < NSTEPS; s++) {
        // ---- layer 0: (16 x 8) @ (8 x 256) + relu -> actA[n][r], col n = tid
        if (s == 0) {
            float a;
#pragma unroll
            for (int r = 0; r < ROWS; r++) {
                a = b0_sh[tid];
#pragma unroll
                for (int k = 0; k < 8; k++)
                    a = fmaf(inp0_sh[r * 8 + k], w0_sh[k * HH + tid], a);
                actA[tid * RS + r] = fmaxf(a, 0.0f);
            }
        } else {
            t_reg += DTC;   // exact sequential fp32 accumulation
            const int i = s - 1;
            const float f_tn = __ldg(tn_store + i);
            const float f_x1 = __ldg(x1_store + i);
            const float f_x2 = __ldg(x2_store + i);
            // features are row-uniform: fold them once
            float base = b0_sh[tid];
            base = fmaf(t_reg, w0_sh[2 * HH + tid], base);
            base = fmaf(f_tn,  w0_sh[3 * HH + tid], base);
            base = fmaf(f_x1,  w0_sh[4 * HH + tid], base);
            base = fmaf(f_x2,  w0_sh[5 * HH + tid], base);
            base = fmaf(f_x1,  w0_sh[6 * HH + tid], base);
            base = fmaf(f_x2,  w0_sh[7 * HH + tid], base);
            const float wa = w0_sh[tid], wb = w0_sh[HH + tid];
#pragma unroll
            for (int r = 0; r < ROWS; r++) {
                float a = fmaf(st_sh[2 * r], wa, fmaf(st_sh[2 * r + 1], wb, base));
                actA[tid * RS + r] = fmaxf(a, 0.0f);
            }
        }
        __syncthreads();

        mlp_layer(actA, actB, wp1, b1_sh, partial, t, q);
        mlp_layer(actB, actA, wp2, b2_sh, partial, t, q);

        // ---- layer 3: (16 x 256) @ (256 x 5), half-warp per row, 16-way split-K
        float acc5[5] = {0.f, 0.f, 0.f, 0.f, 0.f};
#pragma unroll
        for (int kk = 0; kk < 16; kk++) {
            int k = l3l + (kk << 4);
            float a = actA[k * RS + l3r];
#pragma unroll
            for (int m = 0; m < 5; m++) acc5[m] = fmaf(a, w3_sh[k * 5 + m], acc5[m]);
        }
#pragma unroll
        for (int off = 8; off >= 1; off >>= 1) {
#pragma unroll
            for (int m = 0; m < 5; m++)
                acc5[m] += __shfl_down_sync(0xffffffffu, acc5[m], off, 16);
        }

        if (l3l == 0) {
            const int r = l3r;
            const int p = row0 + r;
            float mu0 = acc5[0] + b3_sh[0];
            float mu1 = acc5[1] + b3_sh[1];
            float s11 = softplusf(acc5[2] + b3_sh[2]);
            float s21 = acc5[3] + b3_sh[3];
            float s22 = softplusf(acc5[4] + b3_sh[4]);
            float st0 = st_sh[2 * r], st1 = st_sh[2 * r + 1];
            float2 e = __ldg(reinterpret_cast<const float2*>(path_seed) + s * PP + p);
            float n0v = softplusf(st0 + DTC * mu0 + SQRT_DTC * (s11 * e.x));
            float n1v = softplusf(st1 + DTC * mu1 + SQRT_DTC * (s21 * e.x + s22 * e.y));
            st_sh[2 * r]     = n0v;
            st_sh[2 * r + 1] = n1v;

            // path: out[p*202 + d*101 + time]; step s writes time = s+1
            out[p * 202 + (s + 1)]       = n0v;
            out[p * 202 + 101 + (s + 1)] = n1v;
            if (s == 0) {
                out[p * 202 + 0]   = st0;
                out[p * 202 + 101] = st1;
            }
            int mb = PP * 202 + (p * 100 + s) * 2;
            out[mb + 0] = mu0;
            out[mb + 1] = mu1;
            int sb = PP * 202 + PP * 200 + (p * 100 + s) * 4;
            out[sb + 0] = s11;
            out[sb + 1] = 0.0f;
            out[sb + 2] = s21;
            out[sb + 3] = s22;
        }
        __syncthreads();
    }
}

extern "C" void kernel_launch(void* const* d_in, const int* in_sizes, int n_in,
                              void* d_out, int out_size) {
    const float* W0 = (const float*)d_in[0];
    const float* b0 = (const float*)d_in[1];
    const float* W1 = (const float*)d_in[2];
    const float* b1 = (const float*)d_in[3];
    const float* W2 = (const float*)d_in[4];
    const float* b2 = (const float*)d_in[5];
    const float* W3 = (const float*)d_in[6];
    const float* b3 = (const float*)d_in[7];
    const float* obs_init = (const float*)d_in[8];
    const float* feature_init = (const float*)d_in[9];
    const float* tn_store = (const float*)d_in[10];
    const float* x1_store = (const float*)d_in[11];
    const float* x2_store = (const float*)d_in[12];
    const float* path_seed = (const float*)d_in[13];
    float* out = (float*)d_out;

    cudaFuncSetAttribute(lv_kernel, cudaFuncAttributeMaxDynamicSharedMemorySize,
                         SMEM_BYTES);
    lv_kernel<<<NBLOCKS, NTHREADS, SMEM_BYTES>>>(
        W0, b0, W1, b1, W2, b2, W3, b3, obs_init, feature_init,
        tn_store, x1_store, x2_store, path_seed, out);
}